// round 6
// baseline (speedup 1.0000x reference)
#include <cuda_runtime.h>
#include <cuda_bf16.h>
#include <cstdint>

// Reference epilogue is min(max(min(yn,0),0),1) * (1/(1-p)):
//   min(yn,0) <= 0  ->  max(.,0) == 0  ->  everything after preserves 0.
// Reference output is identically zero, so the kernel is a pure zero-fill of
// d_out (~226.5 MB fp32 stores). DRAM-write bound.
//
// R2: 37.5us @ DRAM 55% (1x STG.128/iter). R5: 34.9us @ 59% (4x STG.128/iter,
// but regs 55 -> occ 44%). R6: 4x STG.256 per iter (sm_100a 256-bit stores,
// half the instructions) + int32 indexing (regs down, occupancy up).

__device__ __forceinline__ void st256_zero(float* p) {
    asm volatile(
        "st.global.v8.f32 [%0], {%1,%1,%1,%1,%1,%1,%1,%1};"
        :: "l"(p), "f"(0.0f) : "memory");
}

__global__ void zero_fill_kernel(float* __restrict__ out, int n) {
    int n8 = n >> 3;                 // 32-byte (8-float) chunks
    const int bsz = blockDim.x;
    const int span = gridDim.x * bsz * 4;
    int base = blockIdx.x * bsz * 4 + threadIdx.x;

    // Fast path: 4 independent coalesced STG.256 per iteration.
    // Store j covers chunk indices [base + j*bsz], lane offset = tid.
    for (; base + 3 * bsz < n8; base += span) {
        st256_zero(out + ((size_t)(base) << 3));
        st256_zero(out + ((size_t)(base + bsz) << 3));
        st256_zero(out + ((size_t)(base + 2 * bsz) << 3));
        st256_zero(out + ((size_t)(base + 3 * bsz) << 3));
    }
    // Guarded epilogue tile (last, possibly partial, stride sequence).
    #pragma unroll
    for (int j = 0; j < 4; j++) {
        int idx = base + j * bsz;
        if (idx < n8) st256_zero(out + ((size_t)idx << 3));
    }
    // Scalar tail (n not divisible by 8).
    int tail_start = n8 << 3;
    int t = tail_start + blockIdx.x * bsz + threadIdx.x;
    if (t < n) out[t] = 0.f;
}

extern "C" void kernel_launch(void* const* d_in, const int* in_sizes, int n_in,
                              void* d_out, int out_size) {
    (void)d_in; (void)in_sizes; (void)n_in;

    int n = out_size;                // fp32 element count (56.6M < 2^31)
    const int threads = 256;
    int blocks = 148 * 16;
    long long n8 = (long long)n >> 3;
    long long needed = (n8 + threads * 4 - 1) / (threads * 4);
    if (needed < blocks) blocks = (int)(needed > 0 ? needed : 1);
    zero_fill_kernel<<<blocks, threads>>>((float*)d_out, n);
}